// round 11
// baseline (speedup 1.0000x reference)
#include <cuda_runtime.h>
#include <cuda_fp16.h>
#include <cstdint>

// ---------------------------------------------------------------------------
// HeteroGAT — bucket CSR, affine single-pass GAT, fp16 features, FFMA2 GEMMs,
// logits fused into GEMM epilogues (+3 tiny 4-col Wal GEMMs). 7 launches.
// ---------------------------------------------------------------------------

#define NNODE  16384
#define IN_DIM 128
#define HID    64
#define OUTF   349
#define NEDGE  262144
#define NEG_SLOPE 0.2f
#define CAP    64

constexpr long long NHF = (long long)NNODE * HID;

constexpr long long OFF_FA0   = 0;                       // half [N][64]
constexpr long long OFF_FP1   = OFF_FA0 + NHF;
constexpr long long OFF_FP2   = OFF_FP1 + NHF;
constexpr long long OFF_F1A   = OFF_FP2 + NHF;
constexpr long long OFF_F1PC  = OFF_F1A + NHF;
constexpr long long OFF_OUTPW = OFF_F1PC + NHF;
constexpr long long OFF_OUTPC = OFF_OUTPW + NHF;
constexpr long long OFF_O1W   = OFF_OUTPC + NHF;
constexpr long long OFF_O1C   = OFF_O1W + NHF;
constexpr long long OFF_HA1   = OFF_O1C + NHF;
constexpr long long OFF_HF    = OFF_HA1 + NHF;
constexpr long long OFF_LA    = OFF_HF + 2 * NHF;        // [N][16] fp32 logits
constexpr long long OFF_LP    = OFF_LA + 16LL * NNODE;
constexpr long long OFF_L1A   = OFF_LP + 16LL * NNODE;
constexpr long long OFF_L1P   = OFF_L1A + 16LL * NNODE;
constexpr long long OFF_WAL   = OFF_L1P + 16LL * NNODE;      // 1280 floats
constexpr long long OFF_CNT   = OFF_WAL + 1280;              // 3*NNODE ints
constexpr long long OFF_SLOT  = OFF_CNT + 3LL * NNODE;       // 3*NNODE*CAP ints
constexpr long long SCRATCH_TOTAL = OFF_SLOT + 3LL * NNODE * CAP + 16;

__device__ __align__(16) float g_scratch[SCRATCH_TOTAL];   // zero-initialized

__device__ __forceinline__ float leaky(float x) {
    return x > 0.f ? x : NEG_SLOPE * x;
}
__device__ __forceinline__ float sel4(float4 v, int h) {
    return h == 0 ? v.x : h == 1 ? v.y : h == 2 ? v.z : v.w;
}

// ---- f32x2 helpers ----
__device__ __forceinline__ unsigned long long pack2(float lo, float hi) {
    unsigned long long r;
    asm("mov.b64 %0, {%1, %2};" : "=l"(r) : "f"(lo), "f"(hi));
    return r;
}
__device__ __forceinline__ unsigned long long dup2(float v) {
    unsigned long long r;
    asm("mov.b64 %0, {%1, %1};" : "=l"(r) : "f"(v));
    return r;
}
__device__ __forceinline__ void unpack2(unsigned long long p, float& lo, float& hi) {
    asm("mov.b64 {%0, %1}, %2;" : "=f"(lo), "=f"(hi) : "l"(p));
}
__device__ __forceinline__ unsigned long long fma2(unsigned long long a,
                                                   unsigned long long b,
                                                   unsigned long long c) {
    unsigned long long d;
    asm("fma.rn.f32x2 %0, %1, %2, %3;" : "=l"(d) : "l"(a), "l"(b), "l"(c));
    return d;
}

// ---------------------------------------------------------------------------
// L1: Wal precompute (only the 3 non-materialized logit sets), 5 blocks.
// wal layout: mat0 er_r [128][4] @0; mat1 er_w [128][4] @512; mat2 er1w [64][4] @1024
// ---------------------------------------------------------------------------
__global__ __launch_bounds__(256) void wal_kernel(
    const float* __restrict__ W0, const float* __restrict__ W1,
    const float* __restrict__ ar0, const float* __restrict__ ar1,
    const float* __restrict__ ntype, float* __restrict__ wal) {
    int id = blockIdx.x * 256 + threadIdx.x;
    if (id >= 1280) return;
    const float* Wm; const float* av; const float* sc; int base;
    if (id < 512)       { Wm = W0 + 2 * 8192; av = ar0 + 128; sc = ntype;       base = 0; }
    else if (id < 1024) { Wm = W0;            av = ar0;       sc = ntype + 128; base = 512; }
    else                { Wm = W1;            av = ar1;       sc = nullptr;     base = 1024; }
    int e = id - base;
    int k = e >> 2, h = e & 3;
    const float* Wr = Wm + (long long)k * 64 + h * 16;
    const float* ar = av + h * 16;
    float sum = 0.f;
#pragma unroll
    for (int d = 0; d < 16; d++) sum += Wr[d] * ar[d];
    wal[base + e] = sum * (sc ? sc[k] : 1.0f);
}

// ---------------------------------------------------------------------------
// GEMM jobs + A-prep
// ---------------------------------------------------------------------------
struct GJob {
    const float* A;
    const float* A2;
    const float* scale;
    const float* ab0;
    const float* ab1;
    int relu;
    const float* W;
    void* C;
    const float* av0; float* lo0;   // epilogue logit dot 0 (out stride 16)
    const float* av1; float* lo1;   // epilogue logit dot 1
};

__device__ __forceinline__ float a_prep(const GJob& jb, long long off, int kc) {
    float v = jb.A[off];
    if (jb.scale) v *= jb.scale[kc];
    if (jb.A2)    v += jb.A2[off];
    if (jb.ab0)   v += jb.ab0[kc];
    if (jb.ab1)   v += jb.ab1[kc];
    if (jb.relu)  v = fmaxf(v, 0.f);
    return v;
}

// ---------------------------------------------------------------------------
// Feature GEMM body: 64x64 tile, FFMA2 inner loop, fp16 epilogue + logit dots
// ---------------------------------------------------------------------------
__device__ __forceinline__ void feat_body(const GJob jb, int K, int tile, int tid,
                                          char* sm) {
    unsigned long long* As2 = (unsigned long long*)sm;          // [32][65]
    float* Ws = (float*)(sm + 32 * 65 * 8);                     // [32][64]
    __half* Ch = (__half*)jb.C;
    int row0 = tile * 64;
    int tr = (tid >> 4) * 4;
    int tc = (tid & 15) * 4;
    unsigned long long acc[4][2] = {};
    for (int kt = 0; kt < K; kt += 32) {
#pragma unroll
        for (int i = 0; i < 8; i++) {
            int idx = tid + i * 256;
            int r = idx >> 5, k = idx & 31;
            int kc = kt + k;
            float v = a_prep(jb, (long long)(row0 + r) * K + kc, kc);
            As2[k * 65 + r] = dup2(v);
        }
#pragma unroll
        for (int i = 0; i < 8; i++) {
            int idx = tid + i * 256;
            int k = idx >> 6, c = idx & 63;
            Ws[k * 64 + c] = jb.W[(long long)(kt + k) * 64 + c];
        }
        __syncthreads();
#pragma unroll
        for (int k = 0; k < 32; k++) {
            float4 w = *(const float4*)&Ws[k * 64 + tc];
            unsigned long long wab = pack2(w.x, w.y);
            unsigned long long wcd = pack2(w.z, w.w);
            unsigned long long a0 = As2[k * 65 + tr];
            unsigned long long a1 = As2[k * 65 + tr + 1];
            unsigned long long a2 = As2[k * 65 + tr + 2];
            unsigned long long a3 = As2[k * 65 + tr + 3];
            acc[0][0] = fma2(a0, wab, acc[0][0]); acc[0][1] = fma2(a0, wcd, acc[0][1]);
            acc[1][0] = fma2(a1, wab, acc[1][0]); acc[1][1] = fma2(a1, wcd, acc[1][1]);
            acc[2][0] = fma2(a2, wab, acc[2][0]); acc[2][1] = fma2(a2, wcd, acc[2][1]);
            acc[3][0] = fma2(a3, wab, acc[3][0]); acc[3][1] = fma2(a3, wcd, acc[3][1]);
        }
        __syncthreads();
    }

    int head = tc >> 4;
    float4 a0v = make_float4(0.f, 0.f, 0.f, 0.f), a1v = a0v;
    if (jb.av0) a0v = *(const float4*)&jb.av0[tc];
    if (jb.av1) a1v = *(const float4*)&jb.av1[tc];

#pragma unroll
    for (int i = 0; i < 4; i++) {
        float c0, c1, c2, c3;
        unpack2(acc[i][0], c0, c1);
        unpack2(acc[i][1], c2, c3);
        int row = row0 + tr + i;
        __half2 h01 = __floats2half2_rn(c0, c1);
        __half2 h23 = __floats2half2_rn(c2, c3);
        uint2 u;
        u.x = *(unsigned*)&h01;
        u.y = *(unsigned*)&h23;
        *(uint2*)&Ch[(long long)row * 64 + tc] = u;
        // fused logit dots: reduce across the 4 consecutive lanes of this head
        if (jb.av0) {
            float s = c0 * a0v.x + c1 * a0v.y + c2 * a0v.z + c3 * a0v.w;
            s += __shfl_xor_sync(0xFFFFFFFFu, s, 1);
            s += __shfl_xor_sync(0xFFFFFFFFu, s, 2);
            if ((tid & 3) == 0) jb.lo0[(long long)row * 16 + head] = s;
        }
        if (jb.av1) {
            float s = c0 * a1v.x + c1 * a1v.y + c2 * a1v.z + c3 * a1v.w;
            s += __shfl_xor_sync(0xFFFFFFFFu, s, 1);
            s += __shfl_xor_sync(0xFFFFFFFFu, s, 2);
            if ((tid & 3) == 0) jb.lo1[(long long)row * 16 + head] = s;
        }
    }
}

// ---------------------------------------------------------------------------
// Narrow 4-col Wal GEMM body (smem-free): thread = (node, head).
// W4 is [K][4]; out written at lo[node*16 + head]. 64 nodes per tile.
// ---------------------------------------------------------------------------
__device__ __forceinline__ void logit4_body(const GJob jb, int K, int tile, int tid) {
    int n = tile * 64 + (tid >> 2);
    int h = tid & 3;
    const float* W4 = jb.W;
    float* lo = jb.lo0;
    long long rb = (long long)n * K;
    float s0 = 0.f, s1 = 0.f;
    for (int k = 0; k < K; k += 8) {
#pragma unroll
        for (int j = 0; j < 8; j += 2) {
            s0 += a_prep(jb, rb + k + j, k + j) * W4[(k + j) * 4 + h];
            s1 += a_prep(jb, rb + k + j + 1, k + j + 1) * W4[(k + j + 1) * 4 + h];
        }
    }
    lo[(long long)n * 16 + h] = s0 + s1;
}

// ---------------------------------------------------------------------------
// L2: bucket scatter + 3 layer-0 feature GEMMs + 2 narrow logit GEMMs
// ---------------------------------------------------------------------------
struct FeatB { GJob j[3]; };
struct Logit2 { GJob j[2]; };

__global__ __launch_bounds__(256) void build_kernel(
    const int* __restrict__ s0, const int* __restrict__ d0,
    const int* __restrict__ s1, const int* __restrict__ d1,
    const int* __restrict__ s2, const int* __restrict__ d2,
    int* __restrict__ cnt, int* __restrict__ slot,
    FeatB fb, Logit2 lb) {
    __shared__ __align__(16) char sm[24832];
    int b = blockIdx.x;
    if (b < 768) {
        int t = b * 256 + threadIdx.x;
#pragma unroll
        for (int u = 0; u < 4; u++) {
            int idx = t + u * 196608;
            int g = idx >> 18;
            int e = idx & (NEDGE - 1);
            const int* ss = (g == 0) ? s0 : (g == 1) ? s1 : s2;
            const int* ds = (g == 0) ? d0 : (g == 1) ? d1 : d2;
            int d = ds[e];
            int pos = atomicAdd(&cnt[g * NNODE + d], 1);
            if (pos < CAP)
                slot[((long long)g * NNODE + d) * CAP + pos] = ss[e];
        }
    } else if (b < 1536) {
        int bb = b - 768;
        feat_body(fb.j[bb >> 8], IN_DIM, bb & 255, threadIdx.x, sm);
    } else {
        int bb = b - 1536;
        logit4_body(lb.j[bb >> 8], IN_DIM, bb & 255, threadIdx.x);
    }
}

// ---------------------------------------------------------------------------
// L4: 2 layer-1 feature GEMMs + 1 narrow logit GEMM
// ---------------------------------------------------------------------------
__global__ __launch_bounds__(256) void l1_kernel(FeatB fb, Logit2 lb) {
    __shared__ __align__(16) char sm[24832];
    int b = blockIdx.x;
    if (b < 512) {
        feat_body(fb.j[b >> 8], HID, b & 255, threadIdx.x, sm);
    } else {
        logit4_body(lb.j[0], HID, b - 512, threadIdx.x);
    }
}

// ---------------------------------------------------------------------------
// Single-pass GAT, bucket slots (R10-proven)
// ---------------------------------------------------------------------------
struct GatJob {
    const int* cnt; const int* slot;
    const float* el; int elS;
    const float* er; int erS;
    const __half2* fs;
    const float* ba; int relu;
    float* out;
};
struct GatB { GatJob j[3]; };

__global__ __launch_bounds__(256) void gat_kernel(GatB p) {
    GatJob jb = p.j[blockIdx.y];
    int w = (blockIdx.x * blockDim.x + threadIdx.x) >> 5;
    int lane = threadIdx.x & 31;
    if (w >= NNODE) return;
    int cnt = jb.cnt[w];
    cnt = cnt < CAP ? cnt : CAP;
    const int* sp = jb.slot + (long long)w * CAP;
    float4 er4 = *(const float4*)(jb.er + (long long)w * jb.erS);
    int head = lane >> 3;
    float eh = sel4(er4, head);

    float accx = 0.f, accy = 0.f, den = 0.f;
    for (int i = 0; i < cnt; i += 4) {
        int4 s4 = *(const int4*)(sp + i);
        float4 q0 = *(const float4*)(jb.el + (long long)s4.x * jb.elS);
        float4 q1 = *(const float4*)(jb.el + (long long)s4.y * jb.elS);
        float4 q2 = *(const float4*)(jb.el + (long long)s4.z * jb.elS);
        float4 q3 = *(const float4*)(jb.el + (long long)s4.w * jb.elS);
        __half2 h0 = jb.fs[(long long)s4.x * 32 + lane];
        __half2 h1 = jb.fs[(long long)s4.y * 32 + lane];
        __half2 h2 = jb.fs[(long long)s4.z * 32 + lane];
        __half2 h3 = jb.fs[(long long)s4.w * 32 + lane];
        float w0 = (i + 0 < cnt) ? __expf(leaky(sel4(q0, head) + eh)) : 0.f;
        float w1 = (i + 1 < cnt) ? __expf(leaky(sel4(q1, head) + eh)) : 0.f;
        float w2 = (i + 2 < cnt) ? __expf(leaky(sel4(q2, head) + eh)) : 0.f;
        float w3 = (i + 3 < cnt) ? __expf(leaky(sel4(q3, head) + eh)) : 0.f;
        den += (w0 + w1) + (w2 + w3);
        float2 f0 = __half22float2(h0);
        float2 f1 = __half22float2(h1);
        float2 f2 = __half22float2(h2);
        float2 f3 = __half22float2(h3);
        accx += f0.x * w0 + f1.x * w1 + f2.x * w2 + f3.x * w3;
        accy += f0.y * w0 + f1.y * w1 + f2.y * w2 + f3.y * w3;
    }

    float inv = 1.f / fmaxf(den, 1e-9f);
    accx *= inv;
    accy *= inv;
    long long ob = (long long)w * HID + 2 * lane;
    if (jb.ba) { accx += jb.ba[2 * lane]; accy += jb.ba[2 * lane + 1]; }
    if (jb.relu) { accx = fmaxf(accx, 0.f); accy = fmaxf(accy, 0.f); }
    *(float2*)&jb.out[ob] = make_float2(accx, accy);
}

// ---------------------------------------------------------------------------
// hf: partial sum + inline scalar C + l2-normalized concat. Also re-zeroes
// cnt for the next kernel_launch call (static init covers the first call).
// ---------------------------------------------------------------------------
__global__ __launch_bounds__(256) void hf_kernel(
    const float* __restrict__ accW, const float* __restrict__ accC,
    const float* __restrict__ b1,
    const float* __restrict__ ln1_gb, const float* __restrict__ attn_w,
    const float* __restrict__ attn_b, const float* __restrict__ ln2_gb,
    const float* __restrict__ ffn_w1, const float* __restrict__ ffn_b1,
    const float* __restrict__ ffn_w2, const float* __restrict__ ffn_b2,
    float* __restrict__ hf, int* __restrict__ cnt) {
    __shared__ float sC;
    int g = blockIdx.x * blockDim.x + threadIdx.x;
    if (g < 3 * NNODE) cnt[g] = 0;   // reset for next launch
    if (threadIdx.x == 0) {
        float y1 = ln1_gb[1];
        float v = y1 * attn_w[2] + attn_b[2];
        float o = v * attn_w[3] + attn_b[3];
        float y2 = ln2_gb[1];
        float f = ffn_b2[0];
        for (int j = 0; j < 16; j++) {
            float z = y2 * ffn_w1[j] + ffn_b1[j];
            float gg = 0.5f * z * (1.0f + erff(z * 0.70710678118654752f));
            f += gg * ffn_w2[j];
        }
        sC = o + f;
    }
    __syncthreads();
    float C = sC;

    int row = g >> 5;
    int lane = g & 31;
    if (row >= NNODE) return;
    long long base = (long long)row * HID;
    float v0 = accW[base + lane]      + accC[base + lane]
             + b1[lane]      + b1[64 + lane];
    float v1 = accW[base + lane + 32] + accC[base + lane + 32]
             + b1[lane + 32] + b1[96 + lane];
    float w0 = v0 + C, w1 = v1 + C;
    float s1 = v0 * v0 + v1 * v1;
    float s2 = w0 * w0 + w1 * w1;
#pragma unroll
    for (int o = 16; o; o >>= 1) {
        s1 += __shfl_xor_sync(0xFFFFFFFFu, s1, o);
        s2 += __shfl_xor_sync(0xFFFFFFFFu, s2, o);
    }
    float i1 = 1.f / fmaxf(sqrtf(s1), 1e-12f);
    float i2 = 1.f / fmaxf(sqrtf(s2), 1e-12f);
    long long hb = (long long)row * 128;
    hf[hb + lane]       = v0 * i1;
    hf[hb + lane + 32]  = v1 * i1;
    hf[hb + 64 + lane]  = w0 * i2;
    hf[hb + 96 + lane]  = w1 * i2;
}

// ---------------------------------------------------------------------------
// Final projection GEMM: FFMA2, fp32 in/out, bias + Ncols guard
// ---------------------------------------------------------------------------
__global__ __launch_bounds__(256) void gemm_final_kernel(
    const float* __restrict__ A, const float* __restrict__ W,
    const float* __restrict__ bias, float* __restrict__ C,
    int K, int Ncols) {
    __shared__ __align__(16) char sm[32 * 65 * 8 + 32 * 64 * 4];
    unsigned long long* As2 = (unsigned long long*)sm;
    float* Ws = (float*)(sm + 32 * 65 * 8);
    int tid = threadIdx.x;
    int row0 = blockIdx.x * 64;
    int col0 = blockIdx.y * 64;
    int tr = (tid >> 4) * 4;
    int tc = (tid & 15) * 4;
    unsigned long long acc[4][2] = {};
    for (int kt = 0; kt < K; kt += 32) {
#pragma unroll
        for (int i = 0; i < 8; i++) {
            int idx = tid + i * 256;
            int r = idx >> 5, k = idx & 31;
            As2[k * 65 + r] = dup2(A[(long long)(row0 + r) * K + kt + k]);
        }
#pragma unroll
        for (int i = 0; i < 8; i++) {
            int idx = tid + i * 256;
            int k = idx >> 6, c = idx & 63;
            int gc = col0 + c;
            Ws[k * 64 + c] = (gc < Ncols) ? W[(long long)(kt + k) * Ncols + gc] : 0.0f;
        }
        __syncthreads();
#pragma unroll
        for (int k = 0; k < 32; k++) {
            float4 w = *(const float4*)&Ws[k * 64 + tc];
            unsigned long long wab = pack2(w.x, w.y);
            unsigned long long wcd = pack2(w.z, w.w);
            unsigned long long a0 = As2[k * 65 + tr];
            unsigned long long a1 = As2[k * 65 + tr + 1];
            unsigned long long a2 = As2[k * 65 + tr + 2];
            unsigned long long a3 = As2[k * 65 + tr + 3];
            acc[0][0] = fma2(a0, wab, acc[0][0]); acc[0][1] = fma2(a0, wcd, acc[0][1]);
            acc[1][0] = fma2(a1, wab, acc[1][0]); acc[1][1] = fma2(a1, wcd, acc[1][1]);
            acc[2][0] = fma2(a2, wab, acc[2][0]); acc[2][1] = fma2(a2, wcd, acc[2][1]);
            acc[3][0] = fma2(a3, wab, acc[3][0]); acc[3][1] = fma2(a3, wcd, acc[3][1]);
        }
        __syncthreads();
    }
#pragma unroll
    for (int i = 0; i < 4; i++) {
        long long r = row0 + tr + i;
        float c0, c1, c2, c3;
        unpack2(acc[i][0], c0, c1);
        unpack2(acc[i][1], c2, c3);
        int c = col0 + tc;
        if (c + 0 < Ncols) C[r * Ncols + c + 0] = c0 + bias[c + 0];
        if (c + 1 < Ncols) C[r * Ncols + c + 1] = c1 + bias[c + 1];
        if (c + 2 < Ncols) C[r * Ncols + c + 2] = c2 + bias[c + 2];
        if (c + 3 < Ncols) C[r * Ncols + c + 3] = c3 + bias[c + 3];
    }
}

// ---------------------------------------------------------------------------
extern "C" void kernel_launch(void* const* d_in, const int* in_sizes, int n_in,
                              void* d_out, int out_size) {
    const float* x_author = (const float*)d_in[0];
    const float* x_paper  = (const float*)d_in[1];
    const float* ntype    = (const float*)d_in[2];
    const float* W0       = (const float*)d_in[3];
    const float* al0      = (const float*)d_in[4];
    const float* ar0      = (const float*)d_in[5];
    const float* b0       = (const float*)d_in[6];
    const float* W1       = (const float*)d_in[7];
    const float* al1      = (const float*)d_in[8];
    const float* ar1      = (const float*)d_in[9];
    const float* b1       = (const float*)d_in[10];
    const float* ln1_gb   = (const float*)d_in[11];
    const float* attn_w   = (const float*)d_in[12];
    const float* attn_b   = (const float*)d_in[13];
    const float* ln2_gb   = (const float*)d_in[14];
    const float* ffn_w1   = (const float*)d_in[15];
    const float* ffn_b1   = (const float*)d_in[16];
    const float* ffn_w2   = (const float*)d_in[17];
    const float* ffn_b2   = (const float*)d_in[18];
    const float* lin_W    = (const float*)d_in[19];
    const float* lin_b    = (const float*)d_in[20];
    const int* src_w = (const int*)d_in[21];
    const int* dst_w = (const int*)d_in[22];
    const int* src_c = (const int*)d_in[23];
    const int* dst_c = (const int*)d_in[24];
    const int* src_r = (const int*)d_in[25];
    const int* dst_r = (const int*)d_in[26];
    float* out = (float*)d_out;

    float* S = nullptr;
    cudaGetSymbolAddress((void**)&S, g_scratch);

    __half2* Fa0  = (__half2*)(S + OFF_FA0);
    __half2* Fp1  = (__half2*)(S + OFF_FP1);
    __half2* Fp2  = (__half2*)(S + OFF_FP2);
    __half2* F1a  = (__half2*)(S + OFF_F1A);
    __half2* F1pc = (__half2*)(S + OFF_F1PC);
    float* outpW = S + OFF_OUTPW;
    float* outpC = S + OFF_OUTPC;
    float* o1w   = S + OFF_O1W;
    float* o1c   = S + OFF_O1C;
    float* ha1   = S + OFF_HA1;
    float* hf    = S + OFF_HF;
    float* LA    = S + OFF_LA;
    float* LP    = S + OFF_LP;
    float* L1A   = S + OFF_L1A;
    float* L1P   = S + OFF_L1P;
    float* wal   = S + OFF_WAL;
    int* cntB  = (int*)(S + OFF_CNT);
    int* slotB = (int*)(S + OFF_SLOT);

    const int* cnt_w = cntB + 0 * NNODE;
    const int* cnt_c = cntB + 1 * NNODE;
    const int* cnt_r = cntB + 2 * NNODE;
    const int* sl_w = slotB + 0LL * NNODE * CAP;
    const int* sl_c = slotB + 1LL * NNODE * CAP;
    const int* sl_r = slotB + 2LL * NNODE * CAP;

    const float* nt0 = ntype;
    const float* nt1 = ntype + IN_DIM;

    // L1: Wal precompute (cnt is zero from static init / previous call's hf)
    wal_kernel<<<5, 256>>>(W0, W1, ar0, ar1, ntype, wal);

    // L2: bucket scatter + layer-0 feature GEMMs (epilogue logits) + 2 narrow
    //     Wal GEMMs, co-launched
    FeatB f0;
    f0.j[0] = { x_author, nullptr, nt0, nullptr, nullptr, 0, W0 + 0 * 8192, Fa0,
                al0 + 0,   LA + 0,  nullptr, nullptr };                 // el_w
    f0.j[1] = { x_paper,  nullptr, nt1, nullptr, nullptr, 0, W0 + 1 * 8192, Fp1,
                al0 + 64,  LP + 4,  ar0 + 64, LP + 8 };                 // el_c, er_c
    f0.j[2] = { x_paper,  nullptr, nt1, nullptr, nullptr, 0, W0 + 2 * 8192, Fp2,
                al0 + 128, LP + 12, nullptr, nullptr };                 // el_r
    Logit2 lg0;
    lg0.j[0] = { x_author, nullptr, nullptr, nullptr, nullptr, 0, wal + 0,   nullptr,
                 nullptr, LA + 4, nullptr, nullptr };                   // er_r
    lg0.j[1] = { x_paper,  nullptr, nullptr, nullptr, nullptr, 0, wal + 512, nullptr,
                 nullptr, LP + 0, nullptr, nullptr };                   // er_w
    build_kernel<<<768 + 768 + 512, 256>>>(src_w, dst_w, src_c, dst_c,
                                           src_r, dst_r, cntB, slotB, f0, lg0);

    // L3: three layer-0 GATs batched
    GatB ga;
    ga.j[0] = { cnt_w, sl_w, LA + 0, 16, LP + 0,  16, Fa0, nullptr,  0, outpW };
    ga.j[1] = { cnt_c, sl_c, LP + 4, 16, LP + 8,  16, Fp1, nullptr,  0, outpC };
    ga.j[2] = { cnt_r, sl_r, LP + 12, 16, LA + 4, 16, Fp2, b0 + 128, 1, ha1 };
    gat_kernel<<<dim3(2048, 3), 256>>>(ga);

    // L4: layer-1 feature GEMMs (epilogue logits) + narrow Wal GEMM (er1w)
    FeatB f1;
    f1.j[0] = { ha1,   nullptr, nullptr, nullptr, nullptr, 0, W1 + 0 * 4096, F1a,
                al1 + 0,  L1A + 0, nullptr, nullptr };                  // el1w
    f1.j[1] = { outpW, outpC,   nullptr, b0,      b0 + 64, 1, W1 + 1 * 4096, F1pc,
                al1 + 64, L1P + 4, ar1 + 64, L1P + 8 };                 // el1c, er1c
    f1.j[2] = { nullptr, nullptr, nullptr, nullptr, nullptr, 0, nullptr, nullptr,
                nullptr, nullptr, nullptr, nullptr };
    Logit2 lg1;
    lg1.j[0] = { outpW, outpC, nullptr, b0, b0 + 64, 1, wal + 1024, nullptr,
                 nullptr, L1P + 0, nullptr, nullptr };                  // er1w
    lg1.j[1] = lg1.j[0];
    l1_kernel<<<512 + 256, 256>>>(f1, lg1);

    // L5: two layer-1 GATs batched
    GatB gc;
    gc.j[0] = { cnt_w, sl_w, L1A + 0, 16, L1P + 0, 16, F1a,  nullptr, 0, o1w };
    gc.j[1] = { cnt_c, sl_c, L1P + 4, 16, L1P + 8, 16, F1pc, nullptr, 0, o1c };
    gc.j[2] = { nullptr, nullptr, nullptr, 0, nullptr, 0, nullptr, nullptr, 0, nullptr };
    gat_kernel<<<dim3(2048, 2), 256>>>(gc);

    // L6: hf (partial sum + inline C + l2norm concat; re-zeroes cnt)
    hf_kernel<<<2048, 256>>>(o1w, o1c, b1, ln1_gb, attn_w, attn_b, ln2_gb,
                             ffn_w1, ffn_b1, ffn_w2, ffn_b2, hf, cntB);

    // L7: final projection (FFMA2)
    gemm_final_kernel<<<dim3(256, 6), 256>>>(hf, lin_W, lin_b, out, 2 * HID, OUTF);
}

// round 12
// speedup vs baseline: 1.0415x; 1.0415x over previous
#include <cuda_runtime.h>
#include <cuda_fp16.h>
#include <cstdint>

// ---------------------------------------------------------------------------
// HeteroGAT — R10 structure (bucket CSR, affine single-pass GAT, fp16
// features, FFMA2 GEMMs, Wal logit GEMMs) with 32-row logit tiles so every
// kernel body fits in 24.8KB smem (occupancy fix). 7 launches.
// ---------------------------------------------------------------------------

#define NNODE  16384
#define IN_DIM 128
#define HID    64
#define OUTF   349
#define NEDGE  262144
#define NEG_SLOPE 0.2f
#define CAP    64

constexpr long long NHF = (long long)NNODE * HID;

constexpr long long OFF_FA0   = 0;                       // half [N][64]
constexpr long long OFF_FP1   = OFF_FA0 + NHF;
constexpr long long OFF_FP2   = OFF_FP1 + NHF;
constexpr long long OFF_F1A   = OFF_FP2 + NHF;
constexpr long long OFF_F1PC  = OFF_F1A + NHF;
constexpr long long OFF_OUTPW = OFF_F1PC + NHF;
constexpr long long OFF_OUTPC = OFF_OUTPW + NHF;
constexpr long long OFF_O1W   = OFF_OUTPC + NHF;
constexpr long long OFF_O1C   = OFF_O1W + NHF;
constexpr long long OFF_HA1   = OFF_O1C + NHF;
constexpr long long OFF_HF    = OFF_HA1 + NHF;
constexpr long long OFF_LA    = OFF_HF + 2 * NHF;        // [N][16] fp32 logits
constexpr long long OFF_LP    = OFF_LA + 16LL * NNODE;
constexpr long long OFF_L1A   = OFF_LP + 16LL * NNODE;
constexpr long long OFF_L1P   = OFF_L1A + 16LL * NNODE;
constexpr long long OFF_WAL   = OFF_L1P + 16LL * NNODE;      // 6144 floats
constexpr long long OFF_CNT   = OFF_WAL + 6144;              // 3*NNODE ints
constexpr long long OFF_SLOT  = OFF_CNT + 3LL * NNODE;       // 3*NNODE*CAP ints
constexpr long long SCRATCH_TOTAL = OFF_SLOT + 3LL * NNODE * CAP + 16;

__device__ __align__(16) float g_scratch[SCRATCH_TOTAL];   // zero-initialized

__device__ __forceinline__ float leaky(float x) {
    return x > 0.f ? x : NEG_SLOPE * x;
}
__device__ __forceinline__ float sel4(float4 v, int h) {
    return h == 0 ? v.x : h == 1 ? v.y : h == 2 ? v.z : v.w;
}

// ---- f32x2 helpers ----
__device__ __forceinline__ unsigned long long pack2(float lo, float hi) {
    unsigned long long r;
    asm("mov.b64 %0, {%1, %2};" : "=l"(r) : "f"(lo), "f"(hi));
    return r;
}
__device__ __forceinline__ unsigned long long dup2(float v) {
    unsigned long long r;
    asm("mov.b64 %0, {%1, %1};" : "=l"(r) : "f"(v));
    return r;
}
__device__ __forceinline__ void unpack2(unsigned long long p, float& lo, float& hi) {
    asm("mov.b64 {%0, %1}, %2;" : "=f"(lo), "=f"(hi) : "l"(p));
}
__device__ __forceinline__ unsigned long long fma2(unsigned long long a,
                                                   unsigned long long b,
                                                   unsigned long long c) {
    unsigned long long d;
    asm("fma.rn.f32x2 %0, %1, %2, %3;" : "=l"(d) : "l"(a), "l"(b), "l"(c));
    return d;
}

// ---------------------------------------------------------------------------
// L1: zero cnt + Wal precompute (10 logit matrices)
// ---------------------------------------------------------------------------
__global__ __launch_bounds__(256) void misc_kernel(
    int* __restrict__ cnt,
    const float* __restrict__ W0, const float* __restrict__ W1,
    const float* __restrict__ al0, const float* __restrict__ ar0,
    const float* __restrict__ al1, const float* __restrict__ ar1,
    const float* __restrict__ ntype, float* __restrict__ wal) {
    int b = blockIdx.x;
    if (b < 192) {
        cnt[b * 256 + threadIdx.x] = 0;
        return;
    }
    int id = (b - 192) * 256 + threadIdx.x;   // 0..6143
    int t, e, base;
    if (id < 2048)      { t = 0; e = id;        base = 0; }
    else if (id < 4096) { t = 1; e = id - 2048; base = 2048; }
    else if (id < 5120) { t = 2; e = id - 4096; base = 4096; }
    else                { t = 3; e = id - 5120; base = 5120; }
    int k = e >> 4, c = e & 15, s = c >> 2, h = c & 3;
    const float* Wm = nullptr;
    const float* av = nullptr;
    const float* sc = nullptr;
    if (t == 0) {
        sc = ntype;
        if (s == 0)      { Wm = W0;             av = al0; }
        else if (s == 1) { Wm = W0 + 2 * 8192;  av = ar0 + 128; }
    } else if (t == 1) {
        sc = ntype + IN_DIM;
        if (s == 0)      { Wm = W0;             av = ar0; }
        else if (s == 1) { Wm = W0 + 8192;      av = al0 + 64; }
        else if (s == 2) { Wm = W0 + 8192;      av = ar0 + 64; }
        else             { Wm = W0 + 2 * 8192;  av = al0 + 128; }
    } else if (t == 2) {
        if (s == 0)      { Wm = W1;             av = al1; }
    } else {
        if (s == 0)      { Wm = W1;             av = ar1; }
        else if (s == 1) { Wm = W1 + 4096;      av = al1 + 64; }
        else if (s == 2) { Wm = W1 + 4096;      av = ar1 + 64; }
    }
    float v = 0.f;
    if (Wm) {
        const float* Wr = Wm + (long long)k * 64 + h * 16;
        const float* ar = av + h * 16;
        float sum = 0.f;
#pragma unroll
        for (int d = 0; d < 16; d++) sum += Wr[d] * ar[d];
        v = sum * (sc ? sc[k] : 1.0f);
    }
    wal[base + k * 16 + c] = v;
}

// ---------------------------------------------------------------------------
// GEMM jobs + A-prep
// ---------------------------------------------------------------------------
struct GJob {
    const float* A;
    const float* A2;
    const float* scale;
    const float* ab0;
    const float* ab1;
    int relu;
    const float* W;
    void* C;
};

__device__ __forceinline__ float a_prep(const GJob& jb, long long off, int kc) {
    float v = jb.A[off];
    if (jb.scale) v *= jb.scale[kc];
    if (jb.A2)    v += jb.A2[off];
    if (jb.ab0)   v += jb.ab0[kc];
    if (jb.ab1)   v += jb.ab1[kc];
    if (jb.relu)  v = fmaxf(v, 0.f);
    return v;
}

// ---------------------------------------------------------------------------
// Feature GEMM body: 64x64 tile, FFMA2 inner loop, fp16 epilogue. 24832B smem.
// ---------------------------------------------------------------------------
__device__ __forceinline__ void feat_body(const GJob jb, int K, int tile, int tid,
                                          char* sm) {
    unsigned long long* As2 = (unsigned long long*)sm;          // [32][65]
    float* Ws = (float*)(sm + 32 * 65 * 8);                     // [32][64]
    __half* Ch = (__half*)jb.C;
    int row0 = tile * 64;
    int tr = (tid >> 4) * 4;
    int tc = (tid & 15) * 4;
    unsigned long long acc[4][2] = {};
    for (int kt = 0; kt < K; kt += 32) {
#pragma unroll
        for (int i = 0; i < 8; i++) {
            int idx = tid + i * 256;
            int r = idx >> 5, k = idx & 31;
            int kc = kt + k;
            float v = a_prep(jb, (long long)(row0 + r) * K + kc, kc);
            As2[k * 65 + r] = dup2(v);
        }
#pragma unroll
        for (int i = 0; i < 8; i++) {
            int idx = tid + i * 256;
            int k = idx >> 6, c = idx & 63;
            Ws[k * 64 + c] = jb.W[(long long)(kt + k) * 64 + c];
        }
        __syncthreads();
#pragma unroll
        for (int k = 0; k < 32; k++) {
            float4 w = *(const float4*)&Ws[k * 64 + tc];
            unsigned long long wab = pack2(w.x, w.y);
            unsigned long long wcd = pack2(w.z, w.w);
            unsigned long long a0 = As2[k * 65 + tr];
            unsigned long long a1 = As2[k * 65 + tr + 1];
            unsigned long long a2 = As2[k * 65 + tr + 2];
            unsigned long long a3 = As2[k * 65 + tr + 3];
            acc[0][0] = fma2(a0, wab, acc[0][0]); acc[0][1] = fma2(a0, wcd, acc[0][1]);
            acc[1][0] = fma2(a1, wab, acc[1][0]); acc[1][1] = fma2(a1, wcd, acc[1][1]);
            acc[2][0] = fma2(a2, wab, acc[2][0]); acc[2][1] = fma2(a2, wcd, acc[2][1]);
            acc[3][0] = fma2(a3, wab, acc[3][0]); acc[3][1] = fma2(a3, wcd, acc[3][1]);
        }
        __syncthreads();
    }
#pragma unroll
    for (int i = 0; i < 4; i++) {
        float c0, c1, c2, c3;
        unpack2(acc[i][0], c0, c1);
        unpack2(acc[i][1], c2, c3);
        __half2 h01 = __floats2half2_rn(c0, c1);
        __half2 h23 = __floats2half2_rn(c2, c3);
        uint2 u;
        u.x = *(unsigned*)&h01;
        u.y = *(unsigned*)&h23;
        *(uint2*)&Ch[(long long)(row0 + tr + i) * 64 + tc] = u;
    }
}

// ---------------------------------------------------------------------------
// Logit GEMM body: 32 rows x 16 cols fp32. smem: As[32][K+2] + Wc[K][16]
//   K=128: 16640 + 8192 = 24832B (== feat_body). K=64: 12544B.
// ---------------------------------------------------------------------------
__device__ __forceinline__ void logit_body(const GJob jb, int K, int kshift,
                                           int tile, int tid, char* sm) {
    int stride = K + 2;
    float* As = (float*)sm;                          // [32][K+2]
    float* Wc = (float*)(sm + 32 * stride * 4);      // [K][16]
    float* Cf = (float*)jb.C;
    int row0 = tile * 32;
    for (int idx = tid; idx < 32 * K; idx += 256) {
        int r = idx >> kshift, k = idx & (K - 1);
        As[r * stride + k] = a_prep(jb, (long long)(row0 + r) * K + k, k);
    }
    for (int idx = tid; idx < K * 16; idx += 256) Wc[idx] = jb.W[idx];
    __syncthreads();
    int c = tid & 15, rg = tid >> 4;                 // 16 groups x 2 rows
    float s0 = 0.f, s1 = 0.f;
    const float* r0 = As + (rg * 2 + 0) * stride;
    const float* r1 = As + (rg * 2 + 1) * stride;
#pragma unroll 4
    for (int k = 0; k < K; k++) {
        float wv = Wc[k * 16 + c];
        s0 += r0[k] * wv;
        s1 += r1[k] * wv;
    }
    long long ob = (long long)(row0 + rg * 2) * 16 + c;
    Cf[ob] = s0;
    Cf[ob + 16] = s1;
}

// ---------------------------------------------------------------------------
// L2: bucket scatter (x4 edges/thread) + 3 feature GEMMs + 2 logit GEMMs
// ---------------------------------------------------------------------------
struct LogitB { GJob j[2]; };
struct FeatB { GJob j[3]; };

__global__ __launch_bounds__(256) void build_kernel(
    const int* __restrict__ s0, const int* __restrict__ d0,
    const int* __restrict__ s1, const int* __restrict__ d1,
    const int* __restrict__ s2, const int* __restrict__ d2,
    int* __restrict__ cnt, int* __restrict__ slot,
    FeatB fb, LogitB lb) {
    __shared__ __align__(16) char sm[24832];
    int b = blockIdx.x;
    if (b < 768) {
        int t = b * 256 + threadIdx.x;
#pragma unroll
        for (int u = 0; u < 4; u++) {
            int idx = t + u * 196608;
            int g = idx >> 18;
            int e = idx & (NEDGE - 1);
            const int* ss = (g == 0) ? s0 : (g == 1) ? s1 : s2;
            const int* ds = (g == 0) ? d0 : (g == 1) ? d1 : d2;
            int d = ds[e];
            int pos = atomicAdd(&cnt[g * NNODE + d], 1);
            if (pos < CAP)
                slot[((long long)g * NNODE + d) * CAP + pos] = ss[e];
        }
    } else if (b < 1536) {
        int bb = b - 768;
        feat_body(fb.j[bb >> 8], IN_DIM, bb & 255, threadIdx.x, sm);
    } else {
        int bb = b - 1536;
        logit_body(lb.j[bb >> 9], IN_DIM, 7, bb & 511, threadIdx.x, sm);
    }
}

// ---------------------------------------------------------------------------
// L4: layer-1 feature + logit GEMMs
// ---------------------------------------------------------------------------
__global__ __launch_bounds__(256) void l1_kernel(FeatB fb, LogitB lb) {
    __shared__ __align__(16) char sm[24832];
    int b = blockIdx.x;
    if (b < 512) {
        feat_body(fb.j[b >> 8], HID, b & 255, threadIdx.x, sm);
    } else {
        int bb = b - 512;
        logit_body(lb.j[bb >> 9], HID, 6, bb & 511, threadIdx.x, sm);
    }
}

// ---------------------------------------------------------------------------
// Single-pass GAT, bucket slots (R10-proven)
// ---------------------------------------------------------------------------
struct GatJob {
    const int* cnt; const int* slot;
    const float* el; int elS;
    const float* er; int erS;
    const __half2* fs;
    const float* ba; int relu;
    float* out;
};
struct GatB { GatJob j[3]; };

__global__ __launch_bounds__(256) void gat_kernel(GatB p) {
    GatJob jb = p.j[blockIdx.y];
    int w = (blockIdx.x * blockDim.x + threadIdx.x) >> 5;
    int lane = threadIdx.x & 31;
    if (w >= NNODE) return;
    int cnt = jb.cnt[w];
    cnt = cnt < CAP ? cnt : CAP;
    const int* sp = jb.slot + (long long)w * CAP;
    float4 er4 = *(const float4*)(jb.er + (long long)w * jb.erS);
    int head = lane >> 3;
    float eh = sel4(er4, head);

    float accx = 0.f, accy = 0.f, den = 0.f;
    for (int i = 0; i < cnt; i += 4) {
        int4 s4 = *(const int4*)(sp + i);
        float4 q0 = *(const float4*)(jb.el + (long long)s4.x * jb.elS);
        float4 q1 = *(const float4*)(jb.el + (long long)s4.y * jb.elS);
        float4 q2 = *(const float4*)(jb.el + (long long)s4.z * jb.elS);
        float4 q3 = *(const float4*)(jb.el + (long long)s4.w * jb.elS);
        __half2 h0 = jb.fs[(long long)s4.x * 32 + lane];
        __half2 h1 = jb.fs[(long long)s4.y * 32 + lane];
        __half2 h2 = jb.fs[(long long)s4.z * 32 + lane];
        __half2 h3 = jb.fs[(long long)s4.w * 32 + lane];
        float w0 = (i + 0 < cnt) ? __expf(leaky(sel4(q0, head) + eh)) : 0.f;
        float w1 = (i + 1 < cnt) ? __expf(leaky(sel4(q1, head) + eh)) : 0.f;
        float w2 = (i + 2 < cnt) ? __expf(leaky(sel4(q2, head) + eh)) : 0.f;
        float w3 = (i + 3 < cnt) ? __expf(leaky(sel4(q3, head) + eh)) : 0.f;
        den += (w0 + w1) + (w2 + w3);
        float2 f0 = __half22float2(h0);
        float2 f1 = __half22float2(h1);
        float2 f2 = __half22float2(h2);
        float2 f3 = __half22float2(h3);
        accx += f0.x * w0 + f1.x * w1 + f2.x * w2 + f3.x * w3;
        accy += f0.y * w0 + f1.y * w1 + f2.y * w2 + f3.y * w3;
    }

    float inv = 1.f / fmaxf(den, 1e-9f);
    accx *= inv;
    accy *= inv;
    long long ob = (long long)w * HID + 2 * lane;
    if (jb.ba) { accx += jb.ba[2 * lane]; accy += jb.ba[2 * lane + 1]; }
    if (jb.relu) { accx = fmaxf(accx, 0.f); accy = fmaxf(accy, 0.f); }
    *(float2*)&jb.out[ob] = make_float2(accx, accy);
}

// ---------------------------------------------------------------------------
// hf: partial sum + inline scalar C + l2-normalized concat
// ---------------------------------------------------------------------------
__global__ __launch_bounds__(256) void hf_kernel(
    const float* __restrict__ accW, const float* __restrict__ accC,
    const float* __restrict__ b1,
    const float* __restrict__ ln1_gb, const float* __restrict__ attn_w,
    const float* __restrict__ attn_b, const float* __restrict__ ln2_gb,
    const float* __restrict__ ffn_w1, const float* __restrict__ ffn_b1,
    const float* __restrict__ ffn_w2, const float* __restrict__ ffn_b2,
    float* __restrict__ hf) {
    __shared__ float sC;
    if (threadIdx.x == 0) {
        float y1 = ln1_gb[1];
        float v = y1 * attn_w[2] + attn_b[2];
        float o = v * attn_w[3] + attn_b[3];
        float y2 = ln2_gb[1];
        float f = ffn_b2[0];
        for (int j = 0; j < 16; j++) {
            float z = y2 * ffn_w1[j] + ffn_b1[j];
            float gg = 0.5f * z * (1.0f + erff(z * 0.70710678118654752f));
            f += gg * ffn_w2[j];
        }
        sC = o + f;
    }
    __syncthreads();
    float C = sC;

    int g = blockIdx.x * blockDim.x + threadIdx.x;
    int row = g >> 5;
    int lane = g & 31;
    if (row >= NNODE) return;
    long long base = (long long)row * HID;
    float v0 = accW[base + lane]      + accC[base + lane]
             + b1[lane]      + b1[64 + lane];
    float v1 = accW[base + lane + 32] + accC[base + lane + 32]
             + b1[lane + 32] + b1[96 + lane];
    float w0 = v0 + C, w1 = v1 + C;
    float s1 = v0 * v0 + v1 * v1;
    float s2 = w0 * w0 + w1 * w1;
#pragma unroll
    for (int o = 16; o; o >>= 1) {
        s1 += __shfl_xor_sync(0xFFFFFFFFu, s1, o);
        s2 += __shfl_xor_sync(0xFFFFFFFFu, s2, o);
    }
    float i1 = 1.f / fmaxf(sqrtf(s1), 1e-12f);
    float i2 = 1.f / fmaxf(sqrtf(s2), 1e-12f);
    long long hb = (long long)row * 128;
    hf[hb + lane]       = v0 * i1;
    hf[hb + lane + 32]  = v1 * i1;
    hf[hb + 64 + lane]  = w0 * i2;
    hf[hb + 96 + lane]  = w1 * i2;
}

// ---------------------------------------------------------------------------
// Final projection GEMM: FFMA2, fp32 in/out, bias + Ncols guard
// ---------------------------------------------------------------------------
__global__ __launch_bounds__(256) void gemm_final_kernel(
    const float* __restrict__ A, const float* __restrict__ W,
    const float* __restrict__ bias, float* __restrict__ C,
    int K, int Ncols) {
    __shared__ __align__(16) char sm[32 * 65 * 8 + 32 * 64 * 4];
    unsigned long long* As2 = (unsigned long long*)sm;
    float* Ws = (float*)(sm + 32 * 65 * 8);
    int tid = threadIdx.x;
    int row0 = blockIdx.x * 64;
    int col0 = blockIdx.y * 64;
    int tr = (tid >> 4) * 4;
    int tc = (tid & 15) * 4;
    unsigned long long acc[4][2] = {};
    for (int kt = 0; kt < K; kt += 32) {
#pragma unroll
        for (int i = 0; i < 8; i++) {
            int idx = tid + i * 256;
            int r = idx >> 5, k = idx & 31;
            As2[k * 65 + r] = dup2(A[(long long)(row0 + r) * K + kt + k]);
        }
#pragma unroll
        for (int i = 0; i < 8; i++) {
            int idx = tid + i * 256;
            int k = idx >> 6, c = idx & 63;
            int gc = col0 + c;
            Ws[k * 64 + c] = (gc < Ncols) ? W[(long long)(kt + k) * Ncols + gc] : 0.0f;
        }
        __syncthreads();
#pragma unroll
        for (int k = 0; k < 32; k++) {
            float4 w = *(const float4*)&Ws[k * 64 + tc];
            unsigned long long wab = pack2(w.x, w.y);
            unsigned long long wcd = pack2(w.z, w.w);
            unsigned long long a0 = As2[k * 65 + tr];
            unsigned long long a1 = As2[k * 65 + tr + 1];
            unsigned long long a2 = As2[k * 65 + tr + 2];
            unsigned long long a3 = As2[k * 65 + tr + 3];
            acc[0][0] = fma2(a0, wab, acc[0][0]); acc[0][1] = fma2(a0, wcd, acc[0][1]);
            acc[1][0] = fma2(a1, wab, acc[1][0]); acc[1][1] = fma2(a1, wcd, acc[1][1]);
            acc[2][0] = fma2(a2, wab, acc[2][0]); acc[2][1] = fma2(a2, wcd, acc[2][1]);
            acc[3][0] = fma2(a3, wab, acc[3][0]); acc[3][1] = fma2(a3, wcd, acc[3][1]);
        }
        __syncthreads();
    }
#pragma unroll
    for (int i = 0; i < 4; i++) {
        long long r = row0 + tr + i;
        float c0, c1, c2, c3;
        unpack2(acc[i][0], c0, c1);
        unpack2(acc[i][1], c2, c3);
        int c = col0 + tc;
        if (c + 0 < Ncols) C[r * Ncols + c + 0] = c0 + bias[c + 0];
        if (c + 1 < Ncols) C[r * Ncols + c + 1] = c1 + bias[c + 1];
        if (c + 2 < Ncols) C[r * Ncols + c + 2] = c2 + bias[c + 2];
        if (c + 3 < Ncols) C[r * Ncols + c + 3] = c3 + bias[c + 3];
    }
}

// ---------------------------------------------------------------------------
extern "C" void kernel_launch(void* const* d_in, const int* in_sizes, int n_in,
                              void* d_out, int out_size) {
    const float* x_author = (const float*)d_in[0];
    const float* x_paper  = (const float*)d_in[1];
    const float* ntype    = (const float*)d_in[2];
    const float* W0       = (const float*)d_in[3];
    const float* al0      = (const float*)d_in[4];
    const float* ar0      = (const float*)d_in[5];
    const float* b0       = (const float*)d_in[6];
    const float* W1       = (const float*)d_in[7];
    const float* al1      = (const float*)d_in[8];
    const float* ar1      = (const float*)d_in[9];
    const float* b1       = (const float*)d_in[10];
    const float* ln1_gb   = (const float*)d_in[11];
    const float* attn_w   = (const float*)d_in[12];
    const float* attn_b   = (const float*)d_in[13];
    const float* ln2_gb   = (const float*)d_in[14];
    const float* ffn_w1   = (const float*)d_in[15];
    const float* ffn_b1   = (const float*)d_in[16];
    const float* ffn_w2   = (const float*)d_in[17];
    const float* ffn_b2   = (const float*)d_in[18];
    const float* lin_W    = (const float*)d_in[19];
    const float* lin_b    = (const float*)d_in[20];
    const int* src_w = (const int*)d_in[21];
    const int* dst_w = (const int*)d_in[22];
    const int* src_c = (const int*)d_in[23];
    const int* dst_c = (const int*)d_in[24];
    const int* src_r = (const int*)d_in[25];
    const int* dst_r = (const int*)d_in[26];
    float* out = (float*)d_out;

    float* S = nullptr;
    cudaGetSymbolAddress((void**)&S, g_scratch);

    __half2* Fa0  = (__half2*)(S + OFF_FA0);
    __half2* Fp1  = (__half2*)(S + OFF_FP1);
    __half2* Fp2  = (__half2*)(S + OFF_FP2);
    __half2* F1a  = (__half2*)(S + OFF_F1A);
    __half2* F1pc = (__half2*)(S + OFF_F1PC);
    float* outpW = S + OFF_OUTPW;
    float* outpC = S + OFF_OUTPC;
    float* o1w   = S + OFF_O1W;
    float* o1c   = S + OFF_O1C;
    float* ha1   = S + OFF_HA1;
    float* hf    = S + OFF_HF;
    float* LA    = S + OFF_LA;
    float* LP    = S + OFF_LP;
    float* L1A   = S + OFF_L1A;
    float* L1P   = S + OFF_L1P;
    float* wal   = S + OFF_WAL;
    int* cntB  = (int*)(S + OFF_CNT);
    int* slotB = (int*)(S + OFF_SLOT);

    const int* cnt_w = cntB + 0 * NNODE;
    const int* cnt_c = cntB + 1 * NNODE;
    const int* cnt_r = cntB + 2 * NNODE;
    const int* sl_w = slotB + 0LL * NNODE * CAP;
    const int* sl_c = slotB + 1LL * NNODE * CAP;
    const int* sl_r = slotB + 2LL * NNODE * CAP;

    const float* nt0 = ntype;
    const float* nt1 = ntype + IN_DIM;

    // L1: zero cnt + Wal precompute
    misc_kernel<<<192 + 24, 256>>>(cntB, W0, W1, al0, ar0, al1, ar1, ntype, wal);

    // L2: bucket scatter + layer-0 feature + logit GEMMs, co-launched
    FeatB f0;
    f0.j[0] = { x_author, nullptr, nt0, nullptr, nullptr, 0, W0 + 0 * 8192, Fa0 };
    f0.j[1] = { x_paper,  nullptr, nt1, nullptr, nullptr, 0, W0 + 1 * 8192, Fp1 };
    f0.j[2] = { x_paper,  nullptr, nt1, nullptr, nullptr, 0, W0 + 2 * 8192, Fp2 };
    LogitB lg0;
    lg0.j[0] = { x_author, nullptr, nullptr, nullptr, nullptr, 0, wal + 0,    LA };
    lg0.j[1] = { x_paper,  nullptr, nullptr, nullptr, nullptr, 0, wal + 2048, LP };
    build_kernel<<<768 + 768 + 1024, 256>>>(src_w, dst_w, src_c, dst_c,
                                            src_r, dst_r, cntB, slotB, f0, lg0);

    // L3: three layer-0 GATs batched (single-pass, bucket slots)
    GatB ga;
    ga.j[0] = { cnt_w, sl_w, LA + 0, 16, LP + 0,  16, Fa0, nullptr,  0, outpW };
    ga.j[1] = { cnt_c, sl_c, LP + 4, 16, LP + 8,  16, Fp1, nullptr,  0, outpC };
    ga.j[2] = { cnt_r, sl_r, LP + 12, 16, LA + 4, 16, Fp2, b0 + 128, 1, ha1 };
    gat_kernel<<<dim3(2048, 3), 256>>>(ga);

    // L4: layer-1 feature + logit GEMMs (hp1 prep fused into A-load)
    FeatB f1;
    f1.j[0] = { ha1,   nullptr, nullptr, nullptr, nullptr, 0, W1 + 0 * 4096, F1a };
    f1.j[1] = { outpW, outpC,   nullptr, b0,      b0 + 64, 1, W1 + 1 * 4096, F1pc };
    f1.j[2] = { nullptr, nullptr, nullptr, nullptr, nullptr, 0, nullptr, nullptr };
    LogitB lg1;
    lg1.j[0] = { ha1,   nullptr, nullptr, nullptr, nullptr, 0, wal + 4096, L1A };
    lg1.j[1] = { outpW, outpC,   nullptr, b0,      b0 + 64, 1, wal + 5120, L1P };
    l1_kernel<<<512 + 1024, 256>>>(f1, lg1);

    // L5: two layer-1 GATs batched
    GatB gc;
    gc.j[0] = { cnt_w, sl_w, L1A + 0, 16, L1P + 0, 16, F1a,  nullptr, 0, o1w };
    gc.j[1] = { cnt_c, sl_c, L1P + 4, 16, L1P + 8, 16, F1pc, nullptr, 0, o1c };
    gc.j[2] = { nullptr, nullptr, nullptr, 0, nullptr, 0, nullptr, nullptr, 0, nullptr };
    gat_kernel<<<dim3(2048, 2), 256>>>(gc);

    // L6: hf (partial sum + inline C + l2-normalized concat)
    hf_kernel<<<2048, 256>>>(o1w, o1c, b1, ln1_gb, attn_w, attn_b, ln2_gb,
                             ffn_w1, ffn_b1, ffn_w2, ffn_b2, hf);

    // L7: final projection (FFMA2)
    gemm_final_kernel<<<dim3(256, 6), 256>>>(hf, lin_W, lin_b, out, 2 * HID, OUTF);
}